// round 14
// baseline (speedup 1.0000x reference)
#include <cuda_runtime.h>
#include <cuda_bf16.h>
#include <stdint.h>

// ---------------- problem constants ----------------
#define NN      100000
#define DD      256
#define PP      1024
#define UU      2048
#define MM      6144          // rows per similarity matrix (2048*3)
#define BLK     48            // 6144/128 row blocks
#define NTILE   1176          // 48*49/2 upper-tri tiles
#define BCE_BLOCKS 128
#define GATHER_BLOCKS ((2 * MM * 32) / 256)   // 1536

#define PITCH   144           // padded smem row bytes (64 bf16 -> 128B + 16 pad)
#define STAGE_OP (128 * PITCH)        // 18432 bytes per tile
#define STAGE_SZ (2 * STAGE_OP)       // 36864 per stage (A, B)
#define NSTAGE  3
#define SMEM_DYN (NSTAGE * STAGE_SZ)  // 110592 -> 2 CTAs/SM

// ---------------- device scratch ----------------
__device__ __align__(16) __nv_bfloat16 g_img[2][MM][DD];  // bf16 rows per matrix
__device__ float  g_spart[2][BLK][MM];          // [mat][slot][row] partial sum of exp
__device__ float  g_tpart[BLK][MM];             // [slot][row] partial sum of dot (sup)
__device__ __align__(16) float g_mid[2][MM][8]; // level-1 row partials (8 slot groups)
__device__ __align__(16) float g_tmid[MM][8];
__device__ float  g_pd[UU][3];                  // unsup pair dots from sim diag
__device__ float  g_bce_part[BCE_BLOCKS][5];

// ---------------- helpers ----------------
__device__ __forceinline__ uint32_t smem_u32(const void* p) {
    uint32_t a;
    asm("{ .reg .u64 t; cvta.to.shared.u64 t, %1; cvt.u32.u64 %0, t; }" : "=r"(a) : "l"(p));
    return a;
}

__device__ __forceinline__ float blk_reduce(float v, float* sm) {
    int tid = threadIdx.x;
    sm[tid] = v; __syncthreads();
#pragma unroll
    for (int s = 128; s > 0; s >>= 1) {
        if (tid < s) sm[tid] += sm[tid + s];
        __syncthreads();
    }
    float r = sm[0]; __syncthreads();
    return r;
}

// ---------------- bf16 row store ----------------
__device__ __forceinline__ void store_b16(int mat, int row, int k0, float4 v) {
    __nv_bfloat16 h0 = __float2bfloat16(v.x), h1 = __float2bfloat16(v.y);
    __nv_bfloat16 h2 = __float2bfloat16(v.z), h3 = __float2bfloat16(v.w);
    uint2 hp;
    hp.x = (uint32_t)__bfloat16_as_ushort(h0) | ((uint32_t)__bfloat16_as_ushort(h1) << 16);
    hp.y = (uint32_t)__bfloat16_as_ushort(h2) | ((uint32_t)__bfloat16_as_ushort(h3) << 16);
    *(uint2*)&g_img[mat][row][k0] = hp;
}

// ---------------- prep: BCE (blocks 0..127) + gather (blocks 128..) fused ----------------
__global__ void __launch_bounds__(256) prep_kernel(const float* __restrict__ fused,
                                                   const float* __restrict__ vlg,
                                                   const float* __restrict__ lab,
                                                   const void* __restrict__ maskp,
                                                   const float* __restrict__ proj,
                                                   const int* __restrict__ pos,
                                                   const int* __restrict__ neg,
                                                   const int* __restrict__ unl,
                                                   int n) {
    if (blockIdx.x < BCE_BLOCKS) {
        // -------- BCE path --------
        __shared__ float sm[256];
        __shared__ int smode;
        if (threadIdx.x == 0) {
            const unsigned char* mb = (const unsigned char*)maskp;
            bool nonbin = false, oddone = false;
            for (int i = 0; i < 256; i++) {
                unsigned char b = mb[i];
                if (b > 1) nonbin = true;
                else if (b == 1 && (i & 3)) oddone = true;
            }
            smode = nonbin ? 2 : (oddone ? 1 : 0);
        }
        __syncthreads();
        int mode = smode;
        float s_main = 0.f, s_v0 = 0.f, s_v1 = 0.f, s_v2 = 0.f, s_cnt = 0.f;
        for (int i = blockIdx.x * 256 + threadIdx.x; i < n; i += BCE_BLOCKS * 256) {
            float mv;
            if (mode == 2)      mv = (((const float*)maskp)[i] != 0.f) ? 1.f : 0.f;
            else if (mode == 1) mv = (((const unsigned char*)maskp)[i] != 0) ? 1.f : 0.f;
            else                mv = (((const int*)maskp)[i] != 0) ? 1.f : 0.f;
            if (mv != 0.f) {
                float y = lab[i];
                float x = fused[i];
                s_main += fmaxf(x, 0.f) - x * y + log1pf(__expf(-fabsf(x)));
                x = vlg[i];
                s_v0 += fmaxf(x, 0.f) - x * y + log1pf(__expf(-fabsf(x)));
                x = vlg[NN + i];
                s_v1 += fmaxf(x, 0.f) - x * y + log1pf(__expf(-fabsf(x)));
                x = vlg[2 * NN + i];
                s_v2 += fmaxf(x, 0.f) - x * y + log1pf(__expf(-fabsf(x)));
                s_cnt += 1.f;
            }
        }
        float r;
        r = blk_reduce(s_main, sm); if (threadIdx.x == 0) g_bce_part[blockIdx.x][0] = r;
        r = blk_reduce(s_v0, sm);   if (threadIdx.x == 0) g_bce_part[blockIdx.x][1] = r;
        r = blk_reduce(s_v1, sm);   if (threadIdx.x == 0) g_bce_part[blockIdx.x][2] = r;
        r = blk_reduce(s_v2, sm);   if (threadIdx.x == 0) g_bce_part[blockIdx.x][3] = r;
        r = blk_reduce(s_cnt, sm);  if (threadIdx.x == 0) g_bce_part[blockIdx.x][4] = r;
    } else {
        // -------- gather path --------
        int b = blockIdx.x - BCE_BLOCKS;
        int gw = (b * 256 + threadIdx.x) >> 5;
        int lane = threadIdx.x & 31;
        if (gw >= 2 * MM) return;
        int mat = (gw >= MM) ? 1 : 0;
        int row = gw - mat * MM;
        int l = row / 3, v = row % 3;
        int idx;
        if (mat == 0) idx = (l < PP) ? pos[l] : neg[l - PP];
        else          idx = unl[l];
        const float4* src = (const float4*)(proj + ((size_t)v * NN + (size_t)idx) * DD);
        float4 x0 = src[lane];
        float4 x1 = src[lane + 32];
        if (mat == 1) {
            float ss = x0.x * x0.x + x0.y * x0.y + x0.z * x0.z + x0.w * x0.w
                     + x1.x * x1.x + x1.y * x1.y + x1.z * x1.z + x1.w * x1.w;
#pragma unroll
            for (int o = 16; o > 0; o >>= 1) ss += __shfl_xor_sync(0xffffffffu, ss, o);
            float inv = 1.f / (sqrtf(ss) + 1e-8f);
            x0.x *= inv; x0.y *= inv; x0.z *= inv; x0.w *= inv;
            x1.x *= inv; x1.y *= inv; x1.z *= inv; x1.w *= inv;
        }
        store_b16(mat, row, 4 * lane, x0);
        store_b16(mat, row, 128 + 4 * lane, x1);
    }
}

// ---------------- HMMA similarity kernel (upper-triangular tiles) ----------------
__device__ __forceinline__ void load_stage(uint32_t sbase, int stage, int m, int I, int J,
                                           int kk, int tid) {
    const __nv_bfloat16* bA = &g_img[m][I * 128][kk * 64];
    const __nv_bfloat16* bB = &g_img[m][J * 128][kk * 64];
    uint32_t sb = sbase + stage * STAGE_SZ;
#pragma unroll
    for (int i = 0; i < 4; i++) {
        int idx = tid * 4 + i;
        int op = idx >> 10, rc = idx & 1023, row = rc >> 3, c16 = rc & 7;
        const __nv_bfloat16* src = (op ? bB : bA) + row * DD + c16 * 8;
        uint32_t dst = sb + op * STAGE_OP + row * PITCH + c16 * 16;
        asm volatile("cp.async.cg.shared.global [%0], [%1], 16;" :: "r"(dst), "l"(src));
    }
    asm volatile("cp.async.commit_group;" ::: "memory");
}

#define MMA8(CC, AA, B0, B1)                                                   \
    asm volatile(                                                              \
        "mma.sync.aligned.m16n8k16.row.col.f32.bf16.bf16.f32 "                 \
        "{%0,%1,%2,%3}, {%4,%5,%6,%7}, {%8,%9}, {%0,%1,%2,%3};"                \
        : "+f"((CC)[0]), "+f"((CC)[1]), "+f"((CC)[2]), "+f"((CC)[3])           \
        : "r"((AA)[0]), "r"((AA)[1]), "r"((AA)[2]), "r"((AA)[3]),              \
          "r"(B0), "r"(B1))

__global__ void __launch_bounds__(512, 2) simmma_kernel() {
    extern __shared__ __align__(16) unsigned char smem[];
    const int tid = threadIdx.x, lane = tid & 31, wid = tid >> 5;
    const int wm = wid >> 2, wn = wid & 3;     // 4x4 warp grid; warp tile 32x32
    const int m = blockIdx.y;
    int t = blockIdx.x, I = 0;
    while (t >= BLK - I) { t -= BLK - I; I++; }
    const int J = I + t;
    uint32_t sbase = smem_u32(smem);

    float C[2][4][4];
#pragma unroll
    for (int a = 0; a < 2; a++)
#pragma unroll
        for (int b = 0; b < 4; b++)
#pragma unroll
            for (int c = 0; c < 4; c++) C[a][b][c] = 0.f;

    load_stage(sbase, 0, m, I, J, 0, tid);
    load_stage(sbase, 1, m, I, J, 1, tid);
#pragma unroll
    for (int kk = 0; kk < 4; kk++) {
        if (kk < 3) asm volatile("cp.async.wait_group 1;" ::: "memory");
        else        asm volatile("cp.async.wait_group 0;" ::: "memory");
        __syncthreads();   // visibility of chunk kk + overwrite safety
        if (kk + 2 < 4) load_stage(sbase, (kk + 2) % NSTAGE, m, I, J, kk + 2, tid);

        uint32_t AH = sbase + (kk % NSTAGE) * STAGE_SZ;
        uint32_t BH = AH + STAGE_OP;
#pragma unroll
        for (int ks = 0; ks < 4; ks++) {
            uint32_t ah[2][4], bh[2][4];
#pragma unroll
            for (int mi = 0; mi < 2; mi++) {
                uint32_t off = (wm * 32 + mi * 16 + (lane & 15)) * PITCH
                             + (ks * 16 + (lane >> 4) * 8) * 2;
                asm volatile("ldmatrix.sync.aligned.m8n8.x4.shared.b16 {%0,%1,%2,%3}, [%4];"
                    : "=r"(ah[mi][0]), "=r"(ah[mi][1]), "=r"(ah[mi][2]), "=r"(ah[mi][3])
                    : "r"(AH + off));
            }
#pragma unroll
            for (int nP = 0; nP < 2; nP++) {
                int g = lane >> 3;
                uint32_t off = (wn * 32 + (nP * 2 + (g >> 1)) * 8 + (lane & 7)) * PITCH
                             + (ks * 16 + (g & 1) * 8) * 2;
                asm volatile("ldmatrix.sync.aligned.m8n8.x4.shared.b16 {%0,%1,%2,%3}, [%4];"
                    : "=r"(bh[nP][0]), "=r"(bh[nP][1]), "=r"(bh[nP][2]), "=r"(bh[nP][3])
                    : "r"(BH + off));
            }
#pragma unroll
            for (int mi = 0; mi < 2; mi++)
#pragma unroll
                for (int ni = 0; ni < 4; ni++) {
                    int p = ni >> 1, q2 = (ni & 1) * 2;
                    MMA8(C[mi][ni], ah[mi], bh[p][q2], bh[p][q2 + 1]);
                }
        }
    }

    // ---------- epilogue: row/col exp & raw sums (smem-reduced, 48-slot) ----------
    const float OFF = (m == 0) ? 5.f : 0.f;
    const bool lm = (I < 24) == (J < 24);
    const bool pdtile = (m == 1) && (J - I <= 1);
    float rE[4], rR[4], cE[8], cR[8];
#pragma unroll
    for (int k = 0; k < 4; k++) { rE[k] = rR[k] = 0.f; }
#pragma unroll
    for (int k = 0; k < 8; k++) { cE[k] = cR[k] = 0.f; }
#pragma unroll
    for (int mi = 0; mi < 2; mi++)
#pragma unroll
        for (int ni = 0; ni < 4; ni++)
#pragma unroll
            for (int f = 0; f < 4; f++) {
                int half = f >> 1, j = f & 1;
                float v = C[mi][ni][f];
                float e = __expf(5.f * v - OFF);
                rE[mi * 2 + half] += e; rR[mi * 2 + half] += v;
                cE[ni * 2 + j]    += e; cR[ni * 2 + j]    += v;
                if (pdtile) {
                    int rg = I * 128 + wm * 32 + mi * 16 + half * 8 + (lane >> 2);
                    int cg = J * 128 + wn * 32 + ni * 8 + (lane & 3) * 2 + j;
                    if (cg > rg && (rg / 3 == cg / 3)) {
                        int u = rg / 3;
                        g_pd[u][(rg % 3) + (cg % 3) - 1] = v;
                    }
                }
            }

    __syncthreads();   // mainloop smem reads done before scratch reuse
    float* scRowE = (float*)smem;          // [128][4]
    float* scRowR = scRowE + 512;          // [128][4]
    float* scColE = scRowR + 512;          // [128][4]
    float* scColR = scColE + 512;          // [128][4]
#pragma unroll
    for (int k = 0; k < 4; k++) {
        float vE = rE[k], vR = rR[k];
        vE += __shfl_xor_sync(0xffffffffu, vE, 1);
        vE += __shfl_xor_sync(0xffffffffu, vE, 2);
        vR += __shfl_xor_sync(0xffffffffu, vR, 1);
        vR += __shfl_xor_sync(0xffffffffu, vR, 2);
        if ((lane & 3) == 0) {
            int r = wm * 32 + (k >> 1) * 16 + (k & 1) * 8 + (lane >> 2);
            scRowE[r * 4 + wn] = vE;
            scRowR[r * 4 + wn] = vR;
        }
    }
#pragma unroll
    for (int k = 0; k < 8; k++) {
        float vE = cE[k], vR = cR[k];
        vE += __shfl_xor_sync(0xffffffffu, vE, 4);
        vE += __shfl_xor_sync(0xffffffffu, vE, 8);
        vE += __shfl_xor_sync(0xffffffffu, vE, 16);
        vR += __shfl_xor_sync(0xffffffffu, vR, 4);
        vR += __shfl_xor_sync(0xffffffffu, vR, 8);
        vR += __shfl_xor_sync(0xffffffffu, vR, 16);
        if (lane < 4) {
            int cc = wn * 32 + (k >> 1) * 8 + (lane & 3) * 2 + (k & 1);
            scColE[cc * 4 + wm] = vE;
            scColR[cc * 4 + wm] = vR;
        }
    }
    __syncthreads();
    if (tid < 128) {
        int r = tid;
        float sE = scRowE[r * 4] + scRowE[r * 4 + 1] + scRowE[r * 4 + 2] + scRowE[r * 4 + 3];
        float sR = scRowR[r * 4] + scRowR[r * 4 + 1] + scRowR[r * 4 + 2] + scRowR[r * 4 + 3];
        g_spart[m][J][I * 128 + r] = sE;
        if (m == 0) g_tpart[J][I * 128 + r] = lm ? sR : 0.f;
    } else if (tid < 256 && I != J) {
        int cc = tid - 128;
        float sE = scColE[cc * 4] + scColE[cc * 4 + 1] + scColE[cc * 4 + 2] + scColE[cc * 4 + 3];
        float sR = scColR[cc * 4] + scColR[cc * 4 + 1] + scColR[cc * 4 + 2] + scColR[cc * 4 + 3];
        g_spart[m][I][J * 128 + cc] = sE;
        if (m == 0) g_tpart[I][J * 128 + cc] = lm ? sR : 0.f;
    }
}

// ---------------- rowsum level 1: 8 slot-groups x 12288 rows ----------------
__global__ void __launch_bounds__(256) rowsum1_kernel() {
    int gid = blockIdx.x * 256 + threadIdx.x;   // 384 blocks -> 98304 threads
    int row12 = gid % (2 * MM);
    int grp = gid / (2 * MM);                   // 0..7
    int m = (row12 >= MM) ? 1 : 0;
    int row = row12 - m * MM;
    float s = 0.f;
#pragma unroll
    for (int o = 0; o < 6; o++) s += g_spart[m][grp * 6 + o][row];
    g_mid[m][row][grp] = s;
    if (m == 0) {
        float t = 0.f;
#pragma unroll
        for (int o = 0; o < 6; o++) t += g_tpart[grp * 6 + o][row];
        g_tmid[row][grp] = t;
    }
}

// ---------------- final: fold level-1 partials + all losses in one CTA ----------------
__global__ void __launch_bounds__(256) final_kernel(float* __restrict__ out) {
    __shared__ float sm[256];
    int tid = threadIdx.x;
    // sup loss: 6144 rows
    float sacc = 0.f;
    for (int r = tid; r < MM; r += 256) {
        float4 a = *(const float4*)&g_mid[0][r][0];
        float4 b = *(const float4*)&g_mid[0][r][4];
        float s = ((a.x + a.y) + (a.z + a.w)) + ((b.x + b.y) + (b.z + b.w));
        float4 c = *(const float4*)&g_tmid[r][0];
        float4 d = *(const float4*)&g_tmid[r][4];
        float t = ((c.x + c.y) + (c.z + c.w)) + ((d.x + d.y) + (d.z + d.w));
        float denom = s - 1.0f + 1e-12f;       // remove diagonal exp(0)=1
        sacc += logf(denom) + 5.0f - (5.0f * t - 5.0f) / 3071.0f;
    }
    float sup_sum = blk_reduce(sacc, sm);
    // unsup loss: 2048 anchors x 3 views
    float uacc = 0.f;
    float e5 = __expf(5.0f);
    for (int u = tid; u < UU; u += 256) {
        float p[3];
#pragma unroll
        for (int k = 0; k < 3; k++) {
            float4 a = *(const float4*)&g_mid[1][3 * u + k][0];
            float4 b = *(const float4*)&g_mid[1][3 * u + k][4];
            p[k] = ((a.x + a.y) + (a.z + a.w)) + ((b.x + b.y) + (b.z + b.w));
        }
        float d01 = g_pd[u][0], d02 = g_pd[u][1], d12 = g_pd[u][2];
        uacc += logf(p[0] - e5 + 1e-12f) - 2.5f * (d01 + d02);
        uacc += logf(p[1] - e5 + 1e-12f) - 2.5f * (d01 + d12);
        uacc += logf(p[2] - e5 + 1e-12f) - 2.5f * (d02 + d12);
    }
    float un_sum = blk_reduce(uacc, sm);
    // BCE merges
    float c0 = blk_reduce((tid < BCE_BLOCKS) ? g_bce_part[tid][0] : 0.f, sm);
    float c1 = blk_reduce((tid < BCE_BLOCKS) ? g_bce_part[tid][1] : 0.f, sm);
    float c2 = blk_reduce((tid < BCE_BLOCKS) ? g_bce_part[tid][2] : 0.f, sm);
    float c3 = blk_reduce((tid < BCE_BLOCKS) ? g_bce_part[tid][3] : 0.f, sm);
    float cnt = blk_reduce((tid < BCE_BLOCKS) ? g_bce_part[tid][4] : 0.f, sm);
    if (tid == 0) {
        float denom = fmaxf(cnt, 1.0f);
        float main_loss = c0 / denom;
        float view_loss = (c1 + c2 + c3) / (3.0f * denom);
        float sup_loss = sup_sum / (float)MM;
        float un_loss = un_sum / (float)MM;
        float total = main_loss + view_loss + sup_loss + 0.2f * un_loss;
        out[0] = total;
        out[1] = main_loss;
        out[2] = view_loss;
        out[3] = sup_loss;
        out[4] = un_loss;
    }
}

// ---------------- launch ----------------
extern "C" void kernel_launch(void* const* d_in, const int* in_sizes, int n_in,
                              void* d_out, int out_size) {
    const float* fused = (const float*)d_in[0];
    const float* vlg   = (const float*)d_in[1];
    const float* proj  = (const float*)d_in[2];
    const float* lab   = (const float*)d_in[3];
    const void*  maskp = d_in[4];
    const int*   pos   = (const int*)d_in[5];
    const int*   neg   = (const int*)d_in[6];
    const int*   unl   = (const int*)d_in[7];
    float* out = (float*)d_out;
    int n = in_sizes[0];

    cudaFuncSetAttribute(simmma_kernel, cudaFuncAttributeMaxDynamicSharedMemorySize, SMEM_DYN);

    prep_kernel<<<BCE_BLOCKS + GATHER_BLOCKS, 256>>>(fused, vlg, lab, maskp,
                                                     proj, pos, neg, unl, n);
    simmma_kernel<<<dim3(NTILE, 2), 512, SMEM_DYN>>>();
    rowsum1_kernel<<<(8 * 2 * MM) / 256, 256>>>();
    final_kernel<<<1, 256>>>(out);
}

// round 15
// speedup vs baseline: 1.0508x; 1.0508x over previous
#include <cuda_runtime.h>
#include <cuda_bf16.h>
#include <stdint.h>

// ---------------- problem constants ----------------
#define NN      100000
#define DD      256
#define PP      1024
#define UU      2048
#define MM      6144          // rows per similarity matrix (2048*3)
#define BLK     48            // 6144/128 row blocks
#define NTILE   1176          // 48*49/2 upper-tri tiles
#define BCE_BLOCKS 128
#define GATHER_BLOCKS ((2 * MM * 32) / 256)   // 1536

#define PITCH   144           // padded smem row bytes (64 bf16 -> 128B + 16 pad)
#define STAGE_OP (128 * PITCH)        // 18432 bytes per tile
#define STAGE_SZ (2 * STAGE_OP)       // 36864 per stage (A, B)
#define NSTAGE  3
#define SMEM_DYN (NSTAGE * STAGE_SZ)  // 110592 -> 2 CTAs/SM

// ---------------- device scratch ----------------
__device__ __align__(16) __nv_bfloat16 g_img[2][MM][DD];  // bf16 rows per matrix
__device__ float  g_spart[2][BLK][MM];          // [mat][slot][row] partial sum of exp
__device__ float  g_tpart[BLK][MM];             // [slot][row] partial sum of dot (sup)
__device__ __align__(16) float g_mid[2][MM][8]; // level-1 row partials (8 slot groups)
__device__ __align__(16) float g_tmid[MM][8];
__device__ float  g_rows[2][MM];                // per-row total exp sums
__device__ float  g_trow[MM];                   // per-row total dot sums (sup)
__device__ float  g_pd[UU][3];                  // unsup pair dots from sim diag
__device__ float  g_bce_part[BCE_BLOCKS][5];

// ---------------- helpers ----------------
__device__ __forceinline__ uint32_t smem_u32(const void* p) {
    uint32_t a;
    asm("{ .reg .u64 t; cvta.to.shared.u64 t, %1; cvt.u32.u64 %0, t; }" : "=r"(a) : "l"(p));
    return a;
}

__device__ __forceinline__ float blk_reduce(float v, float* sm) {
    int tid = threadIdx.x;
    sm[tid] = v; __syncthreads();
#pragma unroll
    for (int s = 128; s > 0; s >>= 1) {
        if (tid < s) sm[tid] += sm[tid + s];
        __syncthreads();
    }
    float r = sm[0]; __syncthreads();
    return r;
}

// ---------------- bf16 row store ----------------
__device__ __forceinline__ void store_b16(int mat, int row, int k0, float4 v) {
    __nv_bfloat16 h0 = __float2bfloat16(v.x), h1 = __float2bfloat16(v.y);
    __nv_bfloat16 h2 = __float2bfloat16(v.z), h3 = __float2bfloat16(v.w);
    uint2 hp;
    hp.x = (uint32_t)__bfloat16_as_ushort(h0) | ((uint32_t)__bfloat16_as_ushort(h1) << 16);
    hp.y = (uint32_t)__bfloat16_as_ushort(h2) | ((uint32_t)__bfloat16_as_ushort(h3) << 16);
    *(uint2*)&g_img[mat][row][k0] = hp;
}

// ---------------- prep: BCE (blocks 0..127) + gather (blocks 128..) fused ----------------
__global__ void __launch_bounds__(256) prep_kernel(const float* __restrict__ fused,
                                                   const float* __restrict__ vlg,
                                                   const float* __restrict__ lab,
                                                   const void* __restrict__ maskp,
                                                   const float* __restrict__ proj,
                                                   const int* __restrict__ pos,
                                                   const int* __restrict__ neg,
                                                   const int* __restrict__ unl,
                                                   int n) {
    if (blockIdx.x < BCE_BLOCKS) {
        // -------- BCE path --------
        __shared__ float sm[256];
        __shared__ int smode;
        if (threadIdx.x == 0) {
            const unsigned char* mb = (const unsigned char*)maskp;
            bool nonbin = false, oddone = false;
            for (int i = 0; i < 256; i++) {
                unsigned char b = mb[i];
                if (b > 1) nonbin = true;
                else if (b == 1 && (i & 3)) oddone = true;
            }
            smode = nonbin ? 2 : (oddone ? 1 : 0);
        }
        __syncthreads();
        int mode = smode;
        float s_main = 0.f, s_v0 = 0.f, s_v1 = 0.f, s_v2 = 0.f, s_cnt = 0.f;
        for (int i = blockIdx.x * 256 + threadIdx.x; i < n; i += BCE_BLOCKS * 256) {
            float mv;
            if (mode == 2)      mv = (((const float*)maskp)[i] != 0.f) ? 1.f : 0.f;
            else if (mode == 1) mv = (((const unsigned char*)maskp)[i] != 0) ? 1.f : 0.f;
            else                mv = (((const int*)maskp)[i] != 0) ? 1.f : 0.f;
            if (mv != 0.f) {
                float y = lab[i];
                float x = fused[i];
                s_main += fmaxf(x, 0.f) - x * y + log1pf(__expf(-fabsf(x)));
                x = vlg[i];
                s_v0 += fmaxf(x, 0.f) - x * y + log1pf(__expf(-fabsf(x)));
                x = vlg[NN + i];
                s_v1 += fmaxf(x, 0.f) - x * y + log1pf(__expf(-fabsf(x)));
                x = vlg[2 * NN + i];
                s_v2 += fmaxf(x, 0.f) - x * y + log1pf(__expf(-fabsf(x)));
                s_cnt += 1.f;
            }
        }
        float r;
        r = blk_reduce(s_main, sm); if (threadIdx.x == 0) g_bce_part[blockIdx.x][0] = r;
        r = blk_reduce(s_v0, sm);   if (threadIdx.x == 0) g_bce_part[blockIdx.x][1] = r;
        r = blk_reduce(s_v1, sm);   if (threadIdx.x == 0) g_bce_part[blockIdx.x][2] = r;
        r = blk_reduce(s_v2, sm);   if (threadIdx.x == 0) g_bce_part[blockIdx.x][3] = r;
        r = blk_reduce(s_cnt, sm);  if (threadIdx.x == 0) g_bce_part[blockIdx.x][4] = r;
    } else {
        // -------- gather path --------
        int b = blockIdx.x - BCE_BLOCKS;
        int gw = (b * 256 + threadIdx.x) >> 5;
        int lane = threadIdx.x & 31;
        if (gw >= 2 * MM) return;
        int mat = (gw >= MM) ? 1 : 0;
        int row = gw - mat * MM;
        int l = row / 3, v = row % 3;
        int idx;
        if (mat == 0) idx = (l < PP) ? pos[l] : neg[l - PP];
        else          idx = unl[l];
        const float4* src = (const float4*)(proj + ((size_t)v * NN + (size_t)idx) * DD);
        float4 x0 = src[lane];
        float4 x1 = src[lane + 32];
        if (mat == 1) {
            float ss = x0.x * x0.x + x0.y * x0.y + x0.z * x0.z + x0.w * x0.w
                     + x1.x * x1.x + x1.y * x1.y + x1.z * x1.z + x1.w * x1.w;
#pragma unroll
            for (int o = 16; o > 0; o >>= 1) ss += __shfl_xor_sync(0xffffffffu, ss, o);
            float inv = 1.f / (sqrtf(ss) + 1e-8f);
            x0.x *= inv; x0.y *= inv; x0.z *= inv; x0.w *= inv;
            x1.x *= inv; x1.y *= inv; x1.z *= inv; x1.w *= inv;
        }
        store_b16(mat, row, 4 * lane, x0);
        store_b16(mat, row, 128 + 4 * lane, x1);
    }
}

// ---------------- HMMA similarity kernel (upper-triangular tiles) ----------------
__device__ __forceinline__ void load_stage(uint32_t sbase, int stage, int m, int I, int J,
                                           int kk, int tid) {
    const __nv_bfloat16* bA = &g_img[m][I * 128][kk * 64];
    const __nv_bfloat16* bB = &g_img[m][J * 128][kk * 64];
    uint32_t sb = sbase + stage * STAGE_SZ;
#pragma unroll
    for (int i = 0; i < 4; i++) {
        int idx = tid * 4 + i;
        int op = idx >> 10, rc = idx & 1023, row = rc >> 3, c16 = rc & 7;
        const __nv_bfloat16* src = (op ? bB : bA) + row * DD + c16 * 8;
        uint32_t dst = sb + op * STAGE_OP + row * PITCH + c16 * 16;
        asm volatile("cp.async.cg.shared.global [%0], [%1], 16;" :: "r"(dst), "l"(src));
    }
    asm volatile("cp.async.commit_group;" ::: "memory");
}

#define MMA8(CC, AA, B0, B1)                                                   \
    asm volatile(                                                              \
        "mma.sync.aligned.m16n8k16.row.col.f32.bf16.bf16.f32 "                 \
        "{%0,%1,%2,%3}, {%4,%5,%6,%7}, {%8,%9}, {%0,%1,%2,%3};"                \
        : "+f"((CC)[0]), "+f"((CC)[1]), "+f"((CC)[2]), "+f"((CC)[3])           \
        : "r"((AA)[0]), "r"((AA)[1]), "r"((AA)[2]), "r"((AA)[3]),              \
          "r"(B0), "r"(B1))

__global__ void __launch_bounds__(512, 2) simmma_kernel() {
    extern __shared__ __align__(16) unsigned char smem[];
    const int tid = threadIdx.x, lane = tid & 31, wid = tid >> 5;
    const int wm = wid >> 2, wn = wid & 3;     // 4x4 warp grid; warp tile 32x32
    const int m = blockIdx.y;
    int t = blockIdx.x, I = 0;
    while (t >= BLK - I) { t -= BLK - I; I++; }
    const int J = I + t;
    uint32_t sbase = smem_u32(smem);

    float C[2][4][4];
#pragma unroll
    for (int a = 0; a < 2; a++)
#pragma unroll
        for (int b = 0; b < 4; b++)
#pragma unroll
            for (int c = 0; c < 4; c++) C[a][b][c] = 0.f;

    load_stage(sbase, 0, m, I, J, 0, tid);
    load_stage(sbase, 1, m, I, J, 1, tid);
#pragma unroll
    for (int kk = 0; kk < 4; kk++) {
        if (kk < 3) asm volatile("cp.async.wait_group 1;" ::: "memory");
        else        asm volatile("cp.async.wait_group 0;" ::: "memory");
        __syncthreads();   // visibility of chunk kk + overwrite safety
        if (kk + 2 < 4) load_stage(sbase, (kk + 2) % NSTAGE, m, I, J, kk + 2, tid);

        uint32_t AH = sbase + (kk % NSTAGE) * STAGE_SZ;
        uint32_t BH = AH + STAGE_OP;
#pragma unroll
        for (int ks = 0; ks < 4; ks++) {
            uint32_t ah[2][4], bh[2][4];
#pragma unroll
            for (int mi = 0; mi < 2; mi++) {
                uint32_t off = (wm * 32 + mi * 16 + (lane & 15)) * PITCH
                             + (ks * 16 + (lane >> 4) * 8) * 2;
                asm volatile("ldmatrix.sync.aligned.m8n8.x4.shared.b16 {%0,%1,%2,%3}, [%4];"
                    : "=r"(ah[mi][0]), "=r"(ah[mi][1]), "=r"(ah[mi][2]), "=r"(ah[mi][3])
                    : "r"(AH + off));
            }
#pragma unroll
            for (int nP = 0; nP < 2; nP++) {
                int g = lane >> 3;
                uint32_t off = (wn * 32 + (nP * 2 + (g >> 1)) * 8 + (lane & 7)) * PITCH
                             + (ks * 16 + (g & 1) * 8) * 2;
                asm volatile("ldmatrix.sync.aligned.m8n8.x4.shared.b16 {%0,%1,%2,%3}, [%4];"
                    : "=r"(bh[nP][0]), "=r"(bh[nP][1]), "=r"(bh[nP][2]), "=r"(bh[nP][3])
                    : "r"(BH + off));
            }
#pragma unroll
            for (int mi = 0; mi < 2; mi++)
#pragma unroll
                for (int ni = 0; ni < 4; ni++) {
                    int p = ni >> 1, q2 = (ni & 1) * 2;
                    MMA8(C[mi][ni], ah[mi], bh[p][q2], bh[p][q2 + 1]);
                }
        }
    }

    // ---------- epilogue: row/col exp & raw sums (smem-reduced, 48-slot) ----------
    const float OFF = (m == 0) ? 5.f : 0.f;
    const bool lm = (I < 24) == (J < 24);
    const bool pdtile = (m == 1) && (J - I <= 1);
    float rE[4], rR[4], cE[8], cR[8];
#pragma unroll
    for (int k = 0; k < 4; k++) { rE[k] = rR[k] = 0.f; }
#pragma unroll
    for (int k = 0; k < 8; k++) { cE[k] = cR[k] = 0.f; }
#pragma unroll
    for (int mi = 0; mi < 2; mi++)
#pragma unroll
        for (int ni = 0; ni < 4; ni++)
#pragma unroll
            for (int f = 0; f < 4; f++) {
                int half = f >> 1, j = f & 1;
                float v = C[mi][ni][f];
                float e = __expf(5.f * v - OFF);
                rE[mi * 2 + half] += e; rR[mi * 2 + half] += v;
                cE[ni * 2 + j]    += e; cR[ni * 2 + j]    += v;
                if (pdtile) {
                    int rg = I * 128 + wm * 32 + mi * 16 + half * 8 + (lane >> 2);
                    int cg = J * 128 + wn * 32 + ni * 8 + (lane & 3) * 2 + j;
                    if (cg > rg && (rg / 3 == cg / 3)) {
                        int u = rg / 3;
                        g_pd[u][(rg % 3) + (cg % 3) - 1] = v;
                    }
                }
            }

    __syncthreads();   // mainloop smem reads done before scratch reuse
    float* scRowE = (float*)smem;          // [128][4]
    float* scRowR = scRowE + 512;          // [128][4]
    float* scColE = scRowR + 512;          // [128][4]
    float* scColR = scColE + 512;          // [128][4]
#pragma unroll
    for (int k = 0; k < 4; k++) {
        float vE = rE[k], vR = rR[k];
        vE += __shfl_xor_sync(0xffffffffu, vE, 1);
        vE += __shfl_xor_sync(0xffffffffu, vE, 2);
        vR += __shfl_xor_sync(0xffffffffu, vR, 1);
        vR += __shfl_xor_sync(0xffffffffu, vR, 2);
        if ((lane & 3) == 0) {
            int r = wm * 32 + (k >> 1) * 16 + (k & 1) * 8 + (lane >> 2);
            scRowE[r * 4 + wn] = vE;
            scRowR[r * 4 + wn] = vR;
        }
    }
#pragma unroll
    for (int k = 0; k < 8; k++) {
        float vE = cE[k], vR = cR[k];
        vE += __shfl_xor_sync(0xffffffffu, vE, 4);
        vE += __shfl_xor_sync(0xffffffffu, vE, 8);
        vE += __shfl_xor_sync(0xffffffffu, vE, 16);
        vR += __shfl_xor_sync(0xffffffffu, vR, 4);
        vR += __shfl_xor_sync(0xffffffffu, vR, 8);
        vR += __shfl_xor_sync(0xffffffffu, vR, 16);
        if (lane < 4) {
            int cc = wn * 32 + (k >> 1) * 8 + (lane & 3) * 2 + (k & 1);
            scColE[cc * 4 + wm] = vE;
            scColR[cc * 4 + wm] = vR;
        }
    }
    __syncthreads();
    if (tid < 128) {
        int r = tid;
        float sE = scRowE[r * 4] + scRowE[r * 4 + 1] + scRowE[r * 4 + 2] + scRowE[r * 4 + 3];
        float sR = scRowR[r * 4] + scRowR[r * 4 + 1] + scRowR[r * 4 + 2] + scRowR[r * 4 + 3];
        g_spart[m][J][I * 128 + r] = sE;
        if (m == 0) g_tpart[J][I * 128 + r] = lm ? sR : 0.f;
    } else if (tid < 256 && I != J) {
        int cc = tid - 128;
        float sE = scColE[cc * 4] + scColE[cc * 4 + 1] + scColE[cc * 4 + 2] + scColE[cc * 4 + 3];
        float sR = scColR[cc * 4] + scColR[cc * 4 + 1] + scColR[cc * 4 + 2] + scColR[cc * 4 + 3];
        g_spart[m][I][J * 128 + cc] = sE;
        if (m == 0) g_tpart[I][J * 128 + cc] = lm ? sR : 0.f;
    }
}

// ---------------- rowsum level 1: 8 slot-groups x 12288 rows ----------------
__global__ void __launch_bounds__(256) rowsum1_kernel() {
    int gid = blockIdx.x * 256 + threadIdx.x;   // 384 blocks -> 98304 threads
    int row12 = gid % (2 * MM);
    int grp = gid / (2 * MM);                   // 0..7
    int m = (row12 >= MM) ? 1 : 0;
    int row = row12 - m * MM;
    float s = 0.f;
#pragma unroll
    for (int o = 0; o < 6; o++) s += g_spart[m][grp * 6 + o][row];
    g_mid[m][row][grp] = s;
    if (m == 0) {
        float t = 0.f;
#pragma unroll
        for (int o = 0; o < 6; o++) t += g_tpart[grp * 6 + o][row];
        g_tmid[row][grp] = t;
    }
}

// ---------------- rowsum level 2: fold 8 partials (contiguous) ----------------
__global__ void __launch_bounds__(256) rowsum2_kernel() {
    int idx = blockIdx.x * 256 + threadIdx.x;   // 48 blocks -> 12288 threads
    int m = (idx >= MM) ? 1 : 0;
    int row = idx - m * MM;
    float4 a = *(const float4*)&g_mid[m][row][0];
    float4 b = *(const float4*)&g_mid[m][row][4];
    g_rows[m][row] = ((a.x + a.y) + (a.z + a.w)) + ((b.x + b.y) + (b.z + b.w));
    if (m == 0) {
        float4 c = *(const float4*)&g_tmid[row][0];
        float4 d = *(const float4*)&g_tmid[row][4];
        g_trow[row] = ((c.x + c.y) + (c.z + c.w)) + ((d.x + d.y) + (d.z + d.w));
    }
}

// ---------------- final: all losses + merge in one CTA (small reads only) ----------------
__global__ void __launch_bounds__(256) final_kernel(float* __restrict__ out) {
    __shared__ float sm[256];
    int tid = threadIdx.x;
    // sup loss: 6144 rows
    float sacc = 0.f;
    for (int r = tid; r < MM; r += 256) {
        float s = g_rows[0][r];
        float t = g_trow[r];
        float denom = s - 1.0f + 1e-12f;       // remove diagonal exp(0)=1
        sacc += logf(denom) + 5.0f - (5.0f * t - 5.0f) / 3071.0f;
    }
    float sup_sum = blk_reduce(sacc, sm);
    // unsup loss: 2048 anchors x 3 views
    float uacc = 0.f;
    float e5 = __expf(5.0f);
    for (int u = tid; u < UU; u += 256) {
        float p0 = g_rows[1][3 * u + 0];
        float p1 = g_rows[1][3 * u + 1];
        float p2 = g_rows[1][3 * u + 2];
        float d01 = g_pd[u][0], d02 = g_pd[u][1], d12 = g_pd[u][2];
        uacc += logf(p0 - e5 + 1e-12f) - 2.5f * (d01 + d02);
        uacc += logf(p1 - e5 + 1e-12f) - 2.5f * (d01 + d12);
        uacc += logf(p2 - e5 + 1e-12f) - 2.5f * (d02 + d12);
    }
    float un_sum = blk_reduce(uacc, sm);
    // BCE merges
    float c0 = blk_reduce((tid < BCE_BLOCKS) ? g_bce_part[tid][0] : 0.f, sm);
    float c1 = blk_reduce((tid < BCE_BLOCKS) ? g_bce_part[tid][1] : 0.f, sm);
    float c2 = blk_reduce((tid < BCE_BLOCKS) ? g_bce_part[tid][2] : 0.f, sm);
    float c3 = blk_reduce((tid < BCE_BLOCKS) ? g_bce_part[tid][3] : 0.f, sm);
    float cnt = blk_reduce((tid < BCE_BLOCKS) ? g_bce_part[tid][4] : 0.f, sm);
    if (tid == 0) {
        float denom = fmaxf(cnt, 1.0f);
        float main_loss = c0 / denom;
        float view_loss = (c1 + c2 + c3) / (3.0f * denom);
        float sup_loss = sup_sum / (float)MM;
        float un_loss = un_sum / (float)MM;
        float total = main_loss + view_loss + sup_loss + 0.2f * un_loss;
        out[0] = total;
        out[1] = main_loss;
        out[2] = view_loss;
        out[3] = sup_loss;
        out[4] = un_loss;
    }
}

// ---------------- launch ----------------
extern "C" void kernel_launch(void* const* d_in, const int* in_sizes, int n_in,
                              void* d_out, int out_size) {
    const float* fused = (const float*)d_in[0];
    const float* vlg   = (const float*)d_in[1];
    const float* proj  = (const float*)d_in[2];
    const float* lab   = (const float*)d_in[3];
    const void*  maskp = d_in[4];
    const int*   pos   = (const int*)d_in[5];
    const int*   neg   = (const int*)d_in[6];
    const int*   unl   = (const int*)d_in[7];
    float* out = (float*)d_out;
    int n = in_sizes[0];

    cudaFuncSetAttribute(simmma_kernel, cudaFuncAttributeMaxDynamicSharedMemorySize, SMEM_DYN);

    prep_kernel<<<BCE_BLOCKS + GATHER_BLOCKS, 256>>>(fused, vlg, lab, maskp,
                                                     proj, pos, neg, unl, n);
    simmma_kernel<<<dim3(NTILE, 2), 512, SMEM_DYN>>>();
    rowsum1_kernel<<<(8 * 2 * MM) / 256, 256>>>();
    rowsum2_kernel<<<(2 * MM) / 256, 256>>>();
    final_kernel<<<1, 256>>>(out);
}

// round 16
// speedup vs baseline: 1.1245x; 1.0702x over previous
#include <cuda_runtime.h>
#include <cuda_bf16.h>
#include <stdint.h>

// ---------------- problem constants ----------------
#define NN      100000
#define DD      256
#define PP      1024
#define UU      2048
#define MM      6144          // rows per similarity matrix (2048*3)
#define BLK     48            // 6144/128 row blocks
#define NTILE   1176          // 48*49/2 upper-tri tiles
#define BCE_BLOCKS 128
#define GATHER_BLOCKS ((2 * MM * 32) / 256)   // 1536

#define PITCH   144           // padded smem row bytes (64 bf16 -> 128B + 16 pad)
#define STAGE_OP (128 * PITCH)        // 18432 bytes per tile
#define STAGE_SZ (2 * STAGE_OP)       // 36864 per stage (A, B)
#define NSTAGE  3
#define SMEM_DYN (NSTAGE * STAGE_SZ)  // 110592 -> 2 CTAs/SM

// ---------------- device scratch ----------------
__device__ __align__(16) __nv_bfloat16 g_img[2][MM][DD];  // bf16 rows per matrix
__device__ float  g_spart[2][BLK][MM];          // [mat][slot][row] partial sum of exp
__device__ float  g_tpart[BLK][MM];             // [slot][row] partial sum of dot (sup)
__device__ __align__(16) float g_mid[2][MM][8]; // level-1 row partials (8 slot groups)
__device__ __align__(16) float g_tmid[MM][8];
__device__ float  g_pd[UU][3];                  // unsup pair dots from sim diag
__device__ float  g_bce_part[BCE_BLOCKS][5];
__device__ float  g_fpart[48];                  // fin block partials (0..23 sup, 24..47 unsup)
__device__ int    g_ctr;                        // fin completion counter (self-resetting)

// ---------------- helpers ----------------
__device__ __forceinline__ uint32_t smem_u32(const void* p) {
    uint32_t a;
    asm("{ .reg .u64 t; cvta.to.shared.u64 t, %1; cvt.u32.u64 %0, t; }" : "=r"(a) : "l"(p));
    return a;
}

__device__ __forceinline__ float blk_reduce(float v, float* sm) {
    int tid = threadIdx.x;
    sm[tid] = v; __syncthreads();
#pragma unroll
    for (int s = 128; s > 0; s >>= 1) {
        if (tid < s) sm[tid] += sm[tid + s];
        __syncthreads();
    }
    float r = sm[0]; __syncthreads();
    return r;
}

// ---------------- bf16 row store ----------------
__device__ __forceinline__ void store_b16(int mat, int row, int k0, float4 v) {
    __nv_bfloat16 h0 = __float2bfloat16(v.x), h1 = __float2bfloat16(v.y);
    __nv_bfloat16 h2 = __float2bfloat16(v.z), h3 = __float2bfloat16(v.w);
    uint2 hp;
    hp.x = (uint32_t)__bfloat16_as_ushort(h0) | ((uint32_t)__bfloat16_as_ushort(h1) << 16);
    hp.y = (uint32_t)__bfloat16_as_ushort(h2) | ((uint32_t)__bfloat16_as_ushort(h3) << 16);
    *(uint2*)&g_img[mat][row][k0] = hp;
}

// ---------------- prep: BCE (blocks 0..127) + gather (blocks 128..) fused ----------------
__global__ void __launch_bounds__(256) prep_kernel(const float* __restrict__ fused,
                                                   const float* __restrict__ vlg,
                                                   const float* __restrict__ lab,
                                                   const void* __restrict__ maskp,
                                                   const float* __restrict__ proj,
                                                   const int* __restrict__ pos,
                                                   const int* __restrict__ neg,
                                                   const int* __restrict__ unl,
                                                   int n) {
    if (blockIdx.x < BCE_BLOCKS) {
        // -------- BCE path --------
        __shared__ float sm[256];
        __shared__ int smode;
        if (threadIdx.x == 0) {
            const unsigned char* mb = (const unsigned char*)maskp;
            bool nonbin = false, oddone = false;
            for (int i = 0; i < 256; i++) {
                unsigned char b = mb[i];
                if (b > 1) nonbin = true;
                else if (b == 1 && (i & 3)) oddone = true;
            }
            smode = nonbin ? 2 : (oddone ? 1 : 0);
        }
        __syncthreads();
        int mode = smode;
        float s_main = 0.f, s_v0 = 0.f, s_v1 = 0.f, s_v2 = 0.f, s_cnt = 0.f;
        for (int i = blockIdx.x * 256 + threadIdx.x; i < n; i += BCE_BLOCKS * 256) {
            float mv;
            if (mode == 2)      mv = (((const float*)maskp)[i] != 0.f) ? 1.f : 0.f;
            else if (mode == 1) mv = (((const unsigned char*)maskp)[i] != 0) ? 1.f : 0.f;
            else                mv = (((const int*)maskp)[i] != 0) ? 1.f : 0.f;
            if (mv != 0.f) {
                float y = lab[i];
                float x = fused[i];
                s_main += fmaxf(x, 0.f) - x * y + log1pf(__expf(-fabsf(x)));
                x = vlg[i];
                s_v0 += fmaxf(x, 0.f) - x * y + log1pf(__expf(-fabsf(x)));
                x = vlg[NN + i];
                s_v1 += fmaxf(x, 0.f) - x * y + log1pf(__expf(-fabsf(x)));
                x = vlg[2 * NN + i];
                s_v2 += fmaxf(x, 0.f) - x * y + log1pf(__expf(-fabsf(x)));
                s_cnt += 1.f;
            }
        }
        float r;
        r = blk_reduce(s_main, sm); if (threadIdx.x == 0) g_bce_part[blockIdx.x][0] = r;
        r = blk_reduce(s_v0, sm);   if (threadIdx.x == 0) g_bce_part[blockIdx.x][1] = r;
        r = blk_reduce(s_v1, sm);   if (threadIdx.x == 0) g_bce_part[blockIdx.x][2] = r;
        r = blk_reduce(s_v2, sm);   if (threadIdx.x == 0) g_bce_part[blockIdx.x][3] = r;
        r = blk_reduce(s_cnt, sm);  if (threadIdx.x == 0) g_bce_part[blockIdx.x][4] = r;
    } else {
        // -------- gather path --------
        int b = blockIdx.x - BCE_BLOCKS;
        int gw = (b * 256 + threadIdx.x) >> 5;
        int lane = threadIdx.x & 31;
        if (gw >= 2 * MM) return;
        int mat = (gw >= MM) ? 1 : 0;
        int row = gw - mat * MM;
        int l = row / 3, v = row % 3;
        int idx;
        if (mat == 0) idx = (l < PP) ? pos[l] : neg[l - PP];
        else          idx = unl[l];
        const float4* src = (const float4*)(proj + ((size_t)v * NN + (size_t)idx) * DD);
        float4 x0 = src[lane];
        float4 x1 = src[lane + 32];
        if (mat == 1) {
            float ss = x0.x * x0.x + x0.y * x0.y + x0.z * x0.z + x0.w * x0.w
                     + x1.x * x1.x + x1.y * x1.y + x1.z * x1.z + x1.w * x1.w;
#pragma unroll
            for (int o = 16; o > 0; o >>= 1) ss += __shfl_xor_sync(0xffffffffu, ss, o);
            float inv = 1.f / (sqrtf(ss) + 1e-8f);
            x0.x *= inv; x0.y *= inv; x0.z *= inv; x0.w *= inv;
            x1.x *= inv; x1.y *= inv; x1.z *= inv; x1.w *= inv;
        }
        store_b16(mat, row, 4 * lane, x0);
        store_b16(mat, row, 128 + 4 * lane, x1);
    }
}

// ---------------- HMMA similarity kernel (upper-triangular tiles) ----------------
__device__ __forceinline__ void load_stage(uint32_t sbase, int stage, int m, int I, int J,
                                           int kk, int tid) {
    const __nv_bfloat16* bA = &g_img[m][I * 128][kk * 64];
    const __nv_bfloat16* bB = &g_img[m][J * 128][kk * 64];
    uint32_t sb = sbase + stage * STAGE_SZ;
#pragma unroll
    for (int i = 0; i < 4; i++) {
        int idx = tid * 4 + i;
        int op = idx >> 10, rc = idx & 1023, row = rc >> 3, c16 = rc & 7;
        const __nv_bfloat16* src = (op ? bB : bA) + row * DD + c16 * 8;
        uint32_t dst = sb + op * STAGE_OP + row * PITCH + c16 * 16;
        asm volatile("cp.async.cg.shared.global [%0], [%1], 16;" :: "r"(dst), "l"(src));
    }
    asm volatile("cp.async.commit_group;" ::: "memory");
}

#define MMA8(CC, AA, B0, B1)                                                   \
    asm volatile(                                                              \
        "mma.sync.aligned.m16n8k16.row.col.f32.bf16.bf16.f32 "                 \
        "{%0,%1,%2,%3}, {%4,%5,%6,%7}, {%8,%9}, {%0,%1,%2,%3};"                \
        : "+f"((CC)[0]), "+f"((CC)[1]), "+f"((CC)[2]), "+f"((CC)[3])           \
        : "r"((AA)[0]), "r"((AA)[1]), "r"((AA)[2]), "r"((AA)[3]),              \
          "r"(B0), "r"(B1))

__global__ void __launch_bounds__(512, 2) simmma_kernel() {
    extern __shared__ __align__(16) unsigned char smem[];
    const int tid = threadIdx.x, lane = tid & 31, wid = tid >> 5;
    const int wm = wid >> 2, wn = wid & 3;     // 4x4 warp grid; warp tile 32x32
    const int m = blockIdx.y;
    int t = blockIdx.x, I = 0;
    while (t >= BLK - I) { t -= BLK - I; I++; }
    const int J = I + t;
    uint32_t sbase = smem_u32(smem);

    float C[2][4][4];
#pragma unroll
    for (int a = 0; a < 2; a++)
#pragma unroll
        for (int b = 0; b < 4; b++)
#pragma unroll
            for (int c = 0; c < 4; c++) C[a][b][c] = 0.f;

    load_stage(sbase, 0, m, I, J, 0, tid);
    load_stage(sbase, 1, m, I, J, 1, tid);
#pragma unroll
    for (int kk = 0; kk < 4; kk++) {
        if (kk < 3) asm volatile("cp.async.wait_group 1;" ::: "memory");
        else        asm volatile("cp.async.wait_group 0;" ::: "memory");
        __syncthreads();   // visibility of chunk kk + overwrite safety
        if (kk + 2 < 4) load_stage(sbase, (kk + 2) % NSTAGE, m, I, J, kk + 2, tid);

        uint32_t AH = sbase + (kk % NSTAGE) * STAGE_SZ;
        uint32_t BH = AH + STAGE_OP;
#pragma unroll
        for (int ks = 0; ks < 4; ks++) {
            uint32_t ah[2][4], bh[2][4];
#pragma unroll
            for (int mi = 0; mi < 2; mi++) {
                uint32_t off = (wm * 32 + mi * 16 + (lane & 15)) * PITCH
                             + (ks * 16 + (lane >> 4) * 8) * 2;
                asm volatile("ldmatrix.sync.aligned.m8n8.x4.shared.b16 {%0,%1,%2,%3}, [%4];"
                    : "=r"(ah[mi][0]), "=r"(ah[mi][1]), "=r"(ah[mi][2]), "=r"(ah[mi][3])
                    : "r"(AH + off));
            }
#pragma unroll
            for (int nP = 0; nP < 2; nP++) {
                int g = lane >> 3;
                uint32_t off = (wn * 32 + (nP * 2 + (g >> 1)) * 8 + (lane & 7)) * PITCH
                             + (ks * 16 + (g & 1) * 8) * 2;
                asm volatile("ldmatrix.sync.aligned.m8n8.x4.shared.b16 {%0,%1,%2,%3}, [%4];"
                    : "=r"(bh[nP][0]), "=r"(bh[nP][1]), "=r"(bh[nP][2]), "=r"(bh[nP][3])
                    : "r"(BH + off));
            }
#pragma unroll
            for (int mi = 0; mi < 2; mi++)
#pragma unroll
                for (int ni = 0; ni < 4; ni++) {
                    int p = ni >> 1, q2 = (ni & 1) * 2;
                    MMA8(C[mi][ni], ah[mi], bh[p][q2], bh[p][q2 + 1]);
                }
        }
    }

    // ---------- epilogue: row/col exp & raw sums (smem-reduced, 48-slot) ----------
    const float OFF = (m == 0) ? 5.f : 0.f;
    const bool lm = (I < 24) == (J < 24);
    const bool pdtile = (m == 1) && (J - I <= 1);
    float rE[4], rR[4], cE[8], cR[8];
#pragma unroll
    for (int k = 0; k < 4; k++) { rE[k] = rR[k] = 0.f; }
#pragma unroll
    for (int k = 0; k < 8; k++) { cE[k] = cR[k] = 0.f; }
#pragma unroll
    for (int mi = 0; mi < 2; mi++)
#pragma unroll
        for (int ni = 0; ni < 4; ni++)
#pragma unroll
            for (int f = 0; f < 4; f++) {
                int half = f >> 1, j = f & 1;
                float v = C[mi][ni][f];
                float e = __expf(5.f * v - OFF);
                rE[mi * 2 + half] += e; rR[mi * 2 + half] += v;
                cE[ni * 2 + j]    += e; cR[ni * 2 + j]    += v;
                if (pdtile) {
                    int rg = I * 128 + wm * 32 + mi * 16 + half * 8 + (lane >> 2);
                    int cg = J * 128 + wn * 32 + ni * 8 + (lane & 3) * 2 + j;
                    if (cg > rg && (rg / 3 == cg / 3)) {
                        int u = rg / 3;
                        g_pd[u][(rg % 3) + (cg % 3) - 1] = v;
                    }
                }
            }

    __syncthreads();   // mainloop smem reads done before scratch reuse
    float* scRowE = (float*)smem;          // [128][4]
    float* scRowR = scRowE + 512;          // [128][4]
    float* scColE = scRowR + 512;          // [128][4]
    float* scColR = scColE + 512;          // [128][4]
#pragma unroll
    for (int k = 0; k < 4; k++) {
        float vE = rE[k], vR = rR[k];
        vE += __shfl_xor_sync(0xffffffffu, vE, 1);
        vE += __shfl_xor_sync(0xffffffffu, vE, 2);
        vR += __shfl_xor_sync(0xffffffffu, vR, 1);
        vR += __shfl_xor_sync(0xffffffffu, vR, 2);
        if ((lane & 3) == 0) {
            int r = wm * 32 + (k >> 1) * 16 + (k & 1) * 8 + (lane >> 2);
            scRowE[r * 4 + wn] = vE;
            scRowR[r * 4 + wn] = vR;
        }
    }
#pragma unroll
    for (int k = 0; k < 8; k++) {
        float vE = cE[k], vR = cR[k];
        vE += __shfl_xor_sync(0xffffffffu, vE, 4);
        vE += __shfl_xor_sync(0xffffffffu, vE, 8);
        vE += __shfl_xor_sync(0xffffffffu, vE, 16);
        vR += __shfl_xor_sync(0xffffffffu, vR, 4);
        vR += __shfl_xor_sync(0xffffffffu, vR, 8);
        vR += __shfl_xor_sync(0xffffffffu, vR, 16);
        if (lane < 4) {
            int cc = wn * 32 + (k >> 1) * 8 + (lane & 3) * 2 + (k & 1);
            scColE[cc * 4 + wm] = vE;
            scColR[cc * 4 + wm] = vR;
        }
    }
    __syncthreads();
    if (tid < 128) {
        int r = tid;
        float sE = scRowE[r * 4] + scRowE[r * 4 + 1] + scRowE[r * 4 + 2] + scRowE[r * 4 + 3];
        float sR = scRowR[r * 4] + scRowR[r * 4 + 1] + scRowR[r * 4 + 2] + scRowR[r * 4 + 3];
        g_spart[m][J][I * 128 + r] = sE;
        if (m == 0) g_tpart[J][I * 128 + r] = lm ? sR : 0.f;
    } else if (tid < 256 && I != J) {
        int cc = tid - 128;
        float sE = scColE[cc * 4] + scColE[cc * 4 + 1] + scColE[cc * 4 + 2] + scColE[cc * 4 + 3];
        float sR = scColR[cc * 4] + scColR[cc * 4 + 1] + scColR[cc * 4 + 2] + scColR[cc * 4 + 3];
        g_spart[m][I][J * 128 + cc] = sE;
        if (m == 0) g_tpart[I][J * 128 + cc] = lm ? sR : 0.f;
    }
}

// ---------------- rowsum level 1: 8 slot-groups x 12288 rows ----------------
__global__ void __launch_bounds__(256) rowsum1_kernel() {
    int gid = blockIdx.x * 256 + threadIdx.x;   // 384 blocks -> 98304 threads
    int row12 = gid % (2 * MM);
    int grp = gid / (2 * MM);                   // 0..7
    int m = (row12 >= MM) ? 1 : 0;
    int row = row12 - m * MM;
    float s = 0.f;
#pragma unroll
    for (int o = 0; o < 6; o++) s += g_spart[m][grp * 6 + o][row];
    g_mid[m][row][grp] = s;
    if (m == 0) {
        float t = 0.f;
#pragma unroll
        for (int o = 0; o < 6; o++) t += g_tpart[grp * 6 + o][row];
        g_tmid[row][grp] = t;
    }
}

// ---------------- fin: fold level-1 partials, losses, last-block merge ----------------
__global__ void __launch_bounds__(256) fin_kernel(float* __restrict__ out) {
    __shared__ float sm[256];
    __shared__ float s_last;
    int b = blockIdx.x, tid = threadIdx.x;   // grid 48
    float acc = 0.f;
    if (b < 24) {
        // sup rows b*256..b*256+255
        int row = b * 256 + tid;
        float4 a0 = *(const float4*)&g_mid[0][row][0];
        float4 a1 = *(const float4*)&g_mid[0][row][4];
        float s = ((a0.x + a0.y) + (a0.z + a0.w)) + ((a1.x + a1.y) + (a1.z + a1.w));
        float4 c0 = *(const float4*)&g_tmid[row][0];
        float4 c1 = *(const float4*)&g_tmid[row][4];
        float t = ((c0.x + c0.y) + (c0.z + c0.w)) + ((c1.x + c1.y) + (c1.z + c1.w));
        float denom = s - 1.0f + 1e-12f;       // remove diagonal exp(0)=1
        acc = logf(denom) + 5.0f - (5.0f * t - 5.0f) / 3071.0f;
    } else {
        // unsup rows (b-24)*256..+255: per-row log term
        int row = (b - 24) * 256 + tid;
        float4 a0 = *(const float4*)&g_mid[1][row][0];
        float4 a1 = *(const float4*)&g_mid[1][row][4];
        float p = ((a0.x + a0.y) + (a0.z + a0.w)) + ((a1.x + a1.y) + (a1.z + a1.w));
        float e5 = __expf(5.0f);
        acc = logf(p - e5 + 1e-12f);
        if (b == 24) {
            // pair-dot correction: - 5 * sum_u (d01 + d02 + d12)
            for (int u = tid; u < UU; u += 256)
                acc -= 5.0f * (g_pd[u][0] + g_pd[u][1] + g_pd[u][2]);
        }
    }
    float r = blk_reduce(acc, sm);
    if (tid == 0) {
        g_fpart[b] = r;
        __threadfence();
        int done = atomicAdd(&g_ctr, 1);
        s_last = (done == 47) ? 1.f : 0.f;
    }
    __syncthreads();
    if (s_last != 0.f) {
        // last block: merge everything
        float sup_sum = blk_reduce((tid < 24) ? g_fpart[tid] : 0.f, sm);
        float un_sum  = blk_reduce((tid >= 24 && tid < 48) ? g_fpart[tid] : 0.f, sm);
        float c0 = blk_reduce((tid < BCE_BLOCKS) ? g_bce_part[tid][0] : 0.f, sm);
        float c1 = blk_reduce((tid < BCE_BLOCKS) ? g_bce_part[tid][1] : 0.f, sm);
        float c2 = blk_reduce((tid < BCE_BLOCKS) ? g_bce_part[tid][2] : 0.f, sm);
        float c3 = blk_reduce((tid < BCE_BLOCKS) ? g_bce_part[tid][3] : 0.f, sm);
        float cnt = blk_reduce((tid < BCE_BLOCKS) ? g_bce_part[tid][4] : 0.f, sm);
        if (tid == 0) {
            float denom = fmaxf(cnt, 1.0f);
            float main_loss = c0 / denom;
            float view_loss = (c1 + c2 + c3) / (3.0f * denom);
            float sup_loss = sup_sum / (float)MM;
            float un_loss = un_sum / (float)MM;
            float total = main_loss + view_loss + sup_loss + 0.2f * un_loss;
            out[0] = total;
            out[1] = main_loss;
            out[2] = view_loss;
            out[3] = sup_loss;
            out[4] = un_loss;
            g_ctr = 0;                       // reset for next graph replay
        }
    }
}

// ---------------- launch ----------------
extern "C" void kernel_launch(void* const* d_in, const int* in_sizes, int n_in,
                              void* d_out, int out_size) {
    const float* fused = (const float*)d_in[0];
    const float* vlg   = (const float*)d_in[1];
    const float* proj  = (const float*)d_in[2];
    const float* lab   = (const float*)d_in[3];
    const void*  maskp = d_in[4];
    const int*   pos   = (const int*)d_in[5];
    const int*   neg   = (const int*)d_in[6];
    const int*   unl   = (const int*)d_in[7];
    float* out = (float*)d_out;
    int n = in_sizes[0];

    cudaFuncSetAttribute(simmma_kernel, cudaFuncAttributeMaxDynamicSharedMemorySize, SMEM_DYN);

    prep_kernel<<<BCE_BLOCKS + GATHER_BLOCKS, 256>>>(fused, vlg, lab, maskp,
                                                     proj, pos, neg, unl, n);
    simmma_kernel<<<dim3(NTILE, 2), 512, SMEM_DYN>>>();
    rowsum1_kernel<<<(8 * 2 * MM) / 256, 256>>>();
    fin_kernel<<<48, 256>>>(out);
}

// round 17
// speedup vs baseline: 1.1477x; 1.0206x over previous
#include <cuda_runtime.h>
#include <cuda_bf16.h>
#include <stdint.h>

// ---------------- problem constants ----------------
#define NN      100000
#define DD      256
#define PP      1024
#define UU      2048
#define MM      6144          // rows per similarity matrix (2048*3)
#define BLK     48            // 6144/128 row blocks
#define NTILE   1176          // 48*49/2 upper-tri tiles
#define BCE_BLOCKS 128
#define GATHER_BLOCKS ((2 * MM * 32) / 256)   // 1536

#define PITCH   144           // padded smem row bytes (64 bf16 -> 128B + 16 pad)
#define STAGE_OP (128 * PITCH)        // 18432 bytes per tile
#define STAGE_SZ (2 * STAGE_OP)       // 36864 per stage (A, B)
#define NSTAGE  3
#define SMEM_DYN (NSTAGE * STAGE_SZ)  // 110592 -> 2 CTAs/SM

// ---------------- device scratch ----------------
__device__ __align__(16) __nv_bfloat16 g_img[2][MM][DD];  // bf16 rows per matrix
__device__ float  g_spart[2][BLK][MM];          // [mat][slot][row] partial sum of exp
__device__ float  g_tpart[BLK][MM];             // [slot][row] partial sum of dot (sup)
__device__ __align__(16) float g_mid[2][MM][8]; // level-1 row partials (8 slot groups)
__device__ __align__(16) float g_tmid[MM][8];
__device__ float  g_pd[UU][3];                  // unsup pair dots from sim diag
__device__ float  g_bce_part[BCE_BLOCKS][5];
__device__ float  g_fpart[48];                  // fin block partials (0..23 sup, 24..47 unsup)
__device__ int    g_ctr;                        // fin completion counter (self-resetting)

// ---------------- helpers ----------------
__device__ __forceinline__ uint32_t smem_u32(const void* p) {
    uint32_t a;
    asm("{ .reg .u64 t; cvta.to.shared.u64 t, %1; cvt.u32.u64 %0, t; }" : "=r"(a) : "l"(p));
    return a;
}

// 3-sync block reduce for blockDim = 256 (8 warps), deterministic fixed tree
__device__ __forceinline__ float blk_reduce(float v, float* sm) {
    int tid = threadIdx.x, lane = tid & 31, w = tid >> 5;
#pragma unroll
    for (int o = 16; o > 0; o >>= 1) v += __shfl_xor_sync(0xffffffffu, v, o);
    if (lane == 0) sm[w] = v;
    __syncthreads();
    if (w == 0) {
        float x = (lane < 8) ? sm[lane] : 0.f;
#pragma unroll
        for (int o = 4; o > 0; o >>= 1) x += __shfl_xor_sync(0xffffffffu, x, o);
        if (lane == 0) sm[0] = x;
    }
    __syncthreads();
    float r = sm[0];
    __syncthreads();   // protect sm reuse across consecutive calls
    return r;
}

// ---------------- bf16 row store ----------------
__device__ __forceinline__ void store_b16(int mat, int row, int k0, float4 v) {
    __nv_bfloat16 h0 = __float2bfloat16(v.x), h1 = __float2bfloat16(v.y);
    __nv_bfloat16 h2 = __float2bfloat16(v.z), h3 = __float2bfloat16(v.w);
    uint2 hp;
    hp.x = (uint32_t)__bfloat16_as_ushort(h0) | ((uint32_t)__bfloat16_as_ushort(h1) << 16);
    hp.y = (uint32_t)__bfloat16_as_ushort(h2) | ((uint32_t)__bfloat16_as_ushort(h3) << 16);
    *(uint2*)&g_img[mat][row][k0] = hp;
}

// ---------------- prep: BCE (blocks 0..127) + gather (blocks 128..) fused ----------------
__global__ void __launch_bounds__(256) prep_kernel(const float* __restrict__ fused,
                                                   const float* __restrict__ vlg,
                                                   const float* __restrict__ lab,
                                                   const void* __restrict__ maskp,
                                                   const float* __restrict__ proj,
                                                   const int* __restrict__ pos,
                                                   const int* __restrict__ neg,
                                                   const int* __restrict__ unl,
                                                   int n) {
    if (blockIdx.x < BCE_BLOCKS) {
        // -------- BCE path --------
        __shared__ float sm[64];
        __shared__ int smode;
        if (threadIdx.x == 0) {
            const unsigned char* mb = (const unsigned char*)maskp;
            bool nonbin = false, oddone = false;
            for (int i = 0; i < 256; i++) {
                unsigned char b = mb[i];
                if (b > 1) nonbin = true;
                else if (b == 1 && (i & 3)) oddone = true;
            }
            smode = nonbin ? 2 : (oddone ? 1 : 0);
        }
        __syncthreads();
        int mode = smode;
        float s_main = 0.f, s_v0 = 0.f, s_v1 = 0.f, s_v2 = 0.f, s_cnt = 0.f;
        for (int i = blockIdx.x * 256 + threadIdx.x; i < n; i += BCE_BLOCKS * 256) {
            float mv;
            if (mode == 2)      mv = (((const float*)maskp)[i] != 0.f) ? 1.f : 0.f;
            else if (mode == 1) mv = (((const unsigned char*)maskp)[i] != 0) ? 1.f : 0.f;
            else                mv = (((const int*)maskp)[i] != 0) ? 1.f : 0.f;
            if (mv != 0.f) {
                float y = lab[i];
                float x = fused[i];
                s_main += fmaxf(x, 0.f) - x * y + log1pf(__expf(-fabsf(x)));
                x = vlg[i];
                s_v0 += fmaxf(x, 0.f) - x * y + log1pf(__expf(-fabsf(x)));
                x = vlg[NN + i];
                s_v1 += fmaxf(x, 0.f) - x * y + log1pf(__expf(-fabsf(x)));
                x = vlg[2 * NN + i];
                s_v2 += fmaxf(x, 0.f) - x * y + log1pf(__expf(-fabsf(x)));
                s_cnt += 1.f;
            }
        }
        float r;
        r = blk_reduce(s_main, sm); if (threadIdx.x == 0) g_bce_part[blockIdx.x][0] = r;
        r = blk_reduce(s_v0, sm);   if (threadIdx.x == 0) g_bce_part[blockIdx.x][1] = r;
        r = blk_reduce(s_v1, sm);   if (threadIdx.x == 0) g_bce_part[blockIdx.x][2] = r;
        r = blk_reduce(s_v2, sm);   if (threadIdx.x == 0) g_bce_part[blockIdx.x][3] = r;
        r = blk_reduce(s_cnt, sm);  if (threadIdx.x == 0) g_bce_part[blockIdx.x][4] = r;
    } else {
        // -------- gather path --------
        int b = blockIdx.x - BCE_BLOCKS;
        int gw = (b * 256 + threadIdx.x) >> 5;
        int lane = threadIdx.x & 31;
        if (gw >= 2 * MM) return;
        int mat = (gw >= MM) ? 1 : 0;
        int row = gw - mat * MM;
        int l = row / 3, v = row % 3;
        int idx;
        if (mat == 0) idx = (l < PP) ? pos[l] : neg[l - PP];
        else          idx = unl[l];
        const float4* src = (const float4*)(proj + ((size_t)v * NN + (size_t)idx) * DD);
        float4 x0 = src[lane];
        float4 x1 = src[lane + 32];
        if (mat == 1) {
            float ss = x0.x * x0.x + x0.y * x0.y + x0.z * x0.z + x0.w * x0.w
                     + x1.x * x1.x + x1.y * x1.y + x1.z * x1.z + x1.w * x1.w;
#pragma unroll
            for (int o = 16; o > 0; o >>= 1) ss += __shfl_xor_sync(0xffffffffu, ss, o);
            float inv = 1.f / (sqrtf(ss) + 1e-8f);
            x0.x *= inv; x0.y *= inv; x0.z *= inv; x0.w *= inv;
            x1.x *= inv; x1.y *= inv; x1.z *= inv; x1.w *= inv;
        }
        store_b16(mat, row, 4 * lane, x0);
        store_b16(mat, row, 128 + 4 * lane, x1);
    }
}

// ---------------- HMMA similarity kernel (upper-triangular tiles) ----------------
__device__ __forceinline__ void load_stage(uint32_t sbase, int stage, int m, int I, int J,
                                           int kk, int tid) {
    const __nv_bfloat16* bA = &g_img[m][I * 128][kk * 64];
    const __nv_bfloat16* bB = &g_img[m][J * 128][kk * 64];
    uint32_t sb = sbase + stage * STAGE_SZ;
#pragma unroll
    for (int i = 0; i < 4; i++) {
        int idx = tid * 4 + i;
        int op = idx >> 10, rc = idx & 1023, row = rc >> 3, c16 = rc & 7;
        const __nv_bfloat16* src = (op ? bB : bA) + row * DD + c16 * 8;
        uint32_t dst = sb + op * STAGE_OP + row * PITCH + c16 * 16;
        asm volatile("cp.async.cg.shared.global [%0], [%1], 16;" :: "r"(dst), "l"(src));
    }
    asm volatile("cp.async.commit_group;" ::: "memory");
}

#define MMA8(CC, AA, B0, B1)                                                   \
    asm volatile(                                                              \
        "mma.sync.aligned.m16n8k16.row.col.f32.bf16.bf16.f32 "                 \
        "{%0,%1,%2,%3}, {%4,%5,%6,%7}, {%8,%9}, {%0,%1,%2,%3};"                \
        : "+f"((CC)[0]), "+f"((CC)[1]), "+f"((CC)[2]), "+f"((CC)[3])           \
        : "r"((AA)[0]), "r"((AA)[1]), "r"((AA)[2]), "r"((AA)[3]),              \
          "r"(B0), "r"(B1))

__global__ void __launch_bounds__(512, 2) simmma_kernel() {
    extern __shared__ __align__(16) unsigned char smem[];
    const int tid = threadIdx.x, lane = tid & 31, wid = tid >> 5;
    const int wm = wid >> 2, wn = wid & 3;     // 4x4 warp grid; warp tile 32x32
    const int m = blockIdx.y;
    int t = blockIdx.x, I = 0;
    while (t >= BLK - I) { t -= BLK - I; I++; }
    const int J = I + t;
    uint32_t sbase = smem_u32(smem);

    float C[2][4][4];
#pragma unroll
    for (int a = 0; a < 2; a++)
#pragma unroll
        for (int b = 0; b < 4; b++)
#pragma unroll
            for (int c = 0; c < 4; c++) C[a][b][c] = 0.f;

    load_stage(sbase, 0, m, I, J, 0, tid);
    load_stage(sbase, 1, m, I, J, 1, tid);
#pragma unroll
    for (int kk = 0; kk < 4; kk++) {
        if (kk < 3) asm volatile("cp.async.wait_group 1;" ::: "memory");
        else        asm volatile("cp.async.wait_group 0;" ::: "memory");
        __syncthreads();   // visibility of chunk kk + overwrite safety
        if (kk + 2 < 4) load_stage(sbase, (kk + 2) % NSTAGE, m, I, J, kk + 2, tid);

        uint32_t AH = sbase + (kk % NSTAGE) * STAGE_SZ;
        uint32_t BH = AH + STAGE_OP;
#pragma unroll
        for (int ks = 0; ks < 4; ks++) {
            uint32_t ah[2][4], bh[2][4];
#pragma unroll
            for (int mi = 0; mi < 2; mi++) {
                uint32_t off = (wm * 32 + mi * 16 + (lane & 15)) * PITCH
                             + (ks * 16 + (lane >> 4) * 8) * 2;
                asm volatile("ldmatrix.sync.aligned.m8n8.x4.shared.b16 {%0,%1,%2,%3}, [%4];"
                    : "=r"(ah[mi][0]), "=r"(ah[mi][1]), "=r"(ah[mi][2]), "=r"(ah[mi][3])
                    : "r"(AH + off));
            }
#pragma unroll
            for (int nP = 0; nP < 2; nP++) {
                int g = lane >> 3;
                uint32_t off = (wn * 32 + (nP * 2 + (g >> 1)) * 8 + (lane & 7)) * PITCH
                             + (ks * 16 + (g & 1) * 8) * 2;
                asm volatile("ldmatrix.sync.aligned.m8n8.x4.shared.b16 {%0,%1,%2,%3}, [%4];"
                    : "=r"(bh[nP][0]), "=r"(bh[nP][1]), "=r"(bh[nP][2]), "=r"(bh[nP][3])
                    : "r"(BH + off));
            }
#pragma unroll
            for (int mi = 0; mi < 2; mi++)
#pragma unroll
                for (int ni = 0; ni < 4; ni++) {
                    int p = ni >> 1, q2 = (ni & 1) * 2;
                    MMA8(C[mi][ni], ah[mi], bh[p][q2], bh[p][q2 + 1]);
                }
        }
    }

    // ---------- epilogue: row/col exp & raw sums (smem-reduced, 48-slot) ----------
    const float OFF = (m == 0) ? 5.f : 0.f;
    const bool lm = (I < 24) == (J < 24);
    const bool pdtile = (m == 1) && (J - I <= 1);
    float rE[4], rR[4], cE[8], cR[8];
#pragma unroll
    for (int k = 0; k < 4; k++) { rE[k] = rR[k] = 0.f; }
#pragma unroll
    for (int k = 0; k < 8; k++) { cE[k] = cR[k] = 0.f; }
#pragma unroll
    for (int mi = 0; mi < 2; mi++)
#pragma unroll
        for (int ni = 0; ni < 4; ni++)
#pragma unroll
            for (int f = 0; f < 4; f++) {
                int half = f >> 1, j = f & 1;
                float v = C[mi][ni][f];
                float e = __expf(5.f * v - OFF);
                rE[mi * 2 + half] += e; rR[mi * 2 + half] += v;
                cE[ni * 2 + j]    += e; cR[ni * 2 + j]    += v;
                if (pdtile) {
                    int rg = I * 128 + wm * 32 + mi * 16 + half * 8 + (lane >> 2);
                    int cg = J * 128 + wn * 32 + ni * 8 + (lane & 3) * 2 + j;
                    if (cg > rg && (rg / 3 == cg / 3)) {
                        int u = rg / 3;
                        g_pd[u][(rg % 3) + (cg % 3) - 1] = v;
                    }
                }
            }

    __syncthreads();   // mainloop smem reads done before scratch reuse
    float* scRowE = (float*)smem;          // [128][4]
    float* scRowR = scRowE + 512;          // [128][4]
    float* scColE = scRowR + 512;          // [128][4]
    float* scColR = scColE + 512;          // [128][4]
#pragma unroll
    for (int k = 0; k < 4; k++) {
        float vE = rE[k], vR = rR[k];
        vE += __shfl_xor_sync(0xffffffffu, vE, 1);
        vE += __shfl_xor_sync(0xffffffffu, vE, 2);
        vR += __shfl_xor_sync(0xffffffffu, vR, 1);
        vR += __shfl_xor_sync(0xffffffffu, vR, 2);
        if ((lane & 3) == 0) {
            int r = wm * 32 + (k >> 1) * 16 + (k & 1) * 8 + (lane >> 2);
            scRowE[r * 4 + wn] = vE;
            scRowR[r * 4 + wn] = vR;
        }
    }
#pragma unroll
    for (int k = 0; k < 8; k++) {
        float vE = cE[k], vR = cR[k];
        vE += __shfl_xor_sync(0xffffffffu, vE, 4);
        vE += __shfl_xor_sync(0xffffffffu, vE, 8);
        vE += __shfl_xor_sync(0xffffffffu, vE, 16);
        vR += __shfl_xor_sync(0xffffffffu, vR, 4);
        vR += __shfl_xor_sync(0xffffffffu, vR, 8);
        vR += __shfl_xor_sync(0xffffffffu, vR, 16);
        if (lane < 4) {
            int cc = wn * 32 + (k >> 1) * 8 + (lane & 3) * 2 + (k & 1);
            scColE[cc * 4 + wm] = vE;
            scColR[cc * 4 + wm] = vR;
        }
    }
    __syncthreads();
    if (tid < 128) {
        int r = tid;
        float sE = scRowE[r * 4] + scRowE[r * 4 + 1] + scRowE[r * 4 + 2] + scRowE[r * 4 + 3];
        float sR = scRowR[r * 4] + scRowR[r * 4 + 1] + scRowR[r * 4 + 2] + scRowR[r * 4 + 3];
        g_spart[m][J][I * 128 + r] = sE;
        if (m == 0) g_tpart[J][I * 128 + r] = lm ? sR : 0.f;
    } else if (tid < 256 && I != J) {
        int cc = tid - 128;
        float sE = scColE[cc * 4] + scColE[cc * 4 + 1] + scColE[cc * 4 + 2] + scColE[cc * 4 + 3];
        float sR = scColR[cc * 4] + scColR[cc * 4 + 1] + scColR[cc * 4 + 2] + scColR[cc * 4 + 3];
        g_spart[m][I][J * 128 + cc] = sE;
        if (m == 0) g_tpart[I][J * 128 + cc] = lm ? sR : 0.f;
    }
}

// ---------------- rowsum level 1: 8 slot-groups x 12288 rows ----------------
__global__ void __launch_bounds__(256) rowsum1_kernel() {
    int gid = blockIdx.x * 256 + threadIdx.x;   // 384 blocks -> 98304 threads
    int row12 = gid % (2 * MM);
    int grp = gid / (2 * MM);                   // 0..7
    int m = (row12 >= MM) ? 1 : 0;
    int row = row12 - m * MM;
    float s = 0.f;
#pragma unroll
    for (int o = 0; o < 6; o++) s += g_spart[m][grp * 6 + o][row];
    g_mid[m][row][grp] = s;
    if (m == 0) {
        float t = 0.f;
#pragma unroll
        for (int o = 0; o < 6; o++) t += g_tpart[grp * 6 + o][row];
        g_tmid[row][grp] = t;
    }
}

// ---------------- fin: fold level-1 partials, losses, last-block merge ----------------
__global__ void __launch_bounds__(256) fin_kernel(float* __restrict__ out) {
    __shared__ float sm[64];
    __shared__ float s_last;
    int b = blockIdx.x, tid = threadIdx.x;   // grid 48
    float acc = 0.f;
    if (b < 24) {
        // sup rows b*256..b*256+255
        int row = b * 256 + tid;
        float4 a0 = *(const float4*)&g_mid[0][row][0];
        float4 a1 = *(const float4*)&g_mid[0][row][4];
        float s = ((a0.x + a0.y) + (a0.z + a0.w)) + ((a1.x + a1.y) + (a1.z + a1.w));
        float4 c0 = *(const float4*)&g_tmid[row][0];
        float4 c1 = *(const float4*)&g_tmid[row][4];
        float t = ((c0.x + c0.y) + (c0.z + c0.w)) + ((c1.x + c1.y) + (c1.z + c1.w));
        float denom = s - 1.0f + 1e-12f;       // remove diagonal exp(0)=1
        acc = logf(denom) + 5.0f - (5.0f * t - 5.0f) / 3071.0f;
    } else {
        // unsup rows (b-24)*256..+255: per-row log term
        int row = (b - 24) * 256 + tid;
        float4 a0 = *(const float4*)&g_mid[1][row][0];
        float4 a1 = *(const float4*)&g_mid[1][row][4];
        float p = ((a0.x + a0.y) + (a0.z + a0.w)) + ((a1.x + a1.y) + (a1.z + a1.w));
        float e5 = __expf(5.0f);
        acc = logf(p - e5 + 1e-12f);
        // pair-dot correction spread over unsup blocks: - 5 * sum_u (d01+d02+d12)
        int g = (b - 24) * 256 + tid;          // 0..6143; first 2048 active
        if (g < UU)
            acc -= 5.0f * (g_pd[g][0] + g_pd[g][1] + g_pd[g][2]);
    }
    float r = blk_reduce(acc, sm);
    if (tid == 0) {
        g_fpart[b] = r;
        __threadfence();
        int done = atomicAdd(&g_ctr, 1);
        s_last = (done == 47) ? 1.f : 0.f;
    }
    __syncthreads();
    if (s_last != 0.f) {
        // last block: merge everything
        float sup_sum = blk_reduce((tid < 24) ? g_fpart[tid] : 0.f, sm);
        float un_sum  = blk_reduce((tid >= 24 && tid < 48) ? g_fpart[tid] : 0.f, sm);
        float c0 = blk_reduce((tid < BCE_BLOCKS) ? g_bce_part[tid][0] : 0.f, sm);
        float c1 = blk_reduce((tid < BCE_BLOCKS) ? g_bce_part[tid][1] : 0.f, sm);
        float c2 = blk_reduce((tid < BCE_BLOCKS) ? g_bce_part[tid][2] : 0.f, sm);
        float c3 = blk_reduce((tid < BCE_BLOCKS) ? g_bce_part[tid][3] : 0.f, sm);
        float cnt = blk_reduce((tid < BCE_BLOCKS) ? g_bce_part[tid][4] : 0.f, sm);
        if (tid == 0) {
            float denom = fmaxf(cnt, 1.0f);
            float main_loss = c0 / denom;
            float view_loss = (c1 + c2 + c3) / (3.0f * denom);
            float sup_loss = sup_sum / (float)MM;
            float un_loss = un_sum / (float)MM;
            float total = main_loss + view_loss + sup_loss + 0.2f * un_loss;
            out[0] = total;
            out[1] = main_loss;
            out[2] = view_loss;
            out[3] = sup_loss;
            out[4] = un_loss;
            g_ctr = 0;                       // reset for next graph replay
        }
    }
}

// ---------------- launch ----------------
extern "C" void kernel_launch(void* const* d_in, const int* in_sizes, int n_in,
                              void* d_out, int out_size) {
    const float* fused = (const float*)d_in[0];
    const float* vlg   = (const float*)d_in[1];
    const float* proj  = (const float*)d_in[2];
    const float* lab   = (const float*)d_in[3];
    const void*  maskp = d_in[4];
    const int*   pos   = (const int*)d_in[5];
    const int*   neg   = (const int*)d_in[6];
    const int*   unl   = (const int*)d_in[7];
    float* out = (float*)d_out;
    int n = in_sizes[0];

    cudaFuncSetAttribute(simmma_kernel, cudaFuncAttributeMaxDynamicSharedMemorySize, SMEM_DYN);

    prep_kernel<<<BCE_BLOCKS + GATHER_BLOCKS, 256>>>(fused, vlg, lab, maskp,
                                                     proj, pos, neg, unl, n);
    simmma_kernel<<<dim3(NTILE, 2), 512, SMEM_DYN>>>();
    rowsum1_kernel<<<(8 * 2 * MM) / 256, 256>>>();
    fin_kernel<<<48, 256>>>(out);
}